// round 3
// baseline (speedup 1.0000x reference)
#include <cuda_runtime.h>
#include <cstdint>

#define C 128

// Flag: 1 if edge_index is int64, 0 if int32. Set by detect kernel each launch
// (deterministic: same input -> same flag).
__device__ int g_idx64;

__global__ void detect_idx_kernel(const void* __restrict__ ei, int n_nodes) {
    if (threadIdx.x == 0 && blockIdx.x == 0) {
        const long long* p = (const long long*)ei;
        int ok = 1;
        #pragma unroll
        for (int i = 0; i < 16; i++) {
            long long v = p[i];
            if (v < 0 || v >= (long long)n_nodes) { ok = 0; }
        }
        g_idx64 = ok;
    }
}

// One warp per edge. Lane l owns floats [4l, 4l+4) of the C=128 row.
//   attn = sum_c x[src][c]*W3[c]*x[dst][c]   (warp shfl reduce)
//   out[dst][c] += attn * x[src][c] * W2[c]  (red.global.add.v4.f32)
__global__ __launch_bounds__(256, 8) void edge_scatter_kernel(
    const float* __restrict__ x,
    const void* __restrict__ ei,
    const float* __restrict__ W2,
    const float* __restrict__ W3,
    float* __restrict__ out,
    int n_edges)
{
    int gwarp = (int)((blockIdx.x * (unsigned)blockDim.x + threadIdx.x) >> 5);
    int lane = threadIdx.x & 31;
    if (gwarp >= n_edges) return;

    long long src, dst;
    if (g_idx64) {
        const long long* p = (const long long*)ei;
        src = __ldg(p + gwarp);
        dst = __ldg(p + n_edges + gwarp);
    } else {
        const int* p = (const int*)ei;
        src = (long long)__ldg(p + gwarp);
        dst = (long long)__ldg(p + n_edges + gwarp);
    }

    // Coalesced 512B row loads (L2-resident: x is only 5.1 MB)
    float4 vs = __ldg((const float4*)(x + src * C) + lane);
    float4 vd = __ldg((const float4*)(x + dst * C) + lane);
    float4 w3 = __ldg((const float4*)W3 + lane);
    float4 w2 = __ldg((const float4*)W2 + lane);

    float part = vs.x * w3.x * vd.x
               + vs.y * w3.y * vd.y
               + vs.z * w3.z * vd.z
               + vs.w * w3.w * vd.w;
    #pragma unroll
    for (int o = 16; o > 0; o >>= 1)
        part += __shfl_xor_sync(0xffffffffu, part, o);

    float4 r;
    r.x = part * vs.x * w2.x;
    r.y = part * vs.y * w2.y;
    r.z = part * vs.z * w2.z;
    r.w = part * vs.w * w2.w;

    float* op = out + dst * C + lane * 4;  // 16B-aligned (C=128)
    asm volatile("red.global.add.v4.f32 [%0], {%1,%2,%3,%4};"
                 :: "l"(op), "f"(r.x), "f"(r.y), "f"(r.z), "f"(r.w)
                 : "memory");
}

extern "C" void kernel_launch(void* const* d_in, const int* in_sizes, int n_in,
                              void* d_out, int out_size) {
    const float* x  = (const float*)d_in[0];
    const void*  ei = d_in[1];
    const float* W2 = (const float*)d_in[2];
    const float* W3 = (const float*)d_in[3];
    float* out = (float*)d_out;

    int n_nodes = in_sizes[0] / C;
    int n_edges = in_sizes[1] / 2;

    // out is poisoned 0xAA by the harness before timing; zero it every call.
    cudaMemsetAsync(out, 0, (size_t)out_size * sizeof(float), 0);

    detect_idx_kernel<<<1, 32>>>(ei, n_nodes);

    int warps_per_block = 256 / 32;
    int blocks = (n_edges + warps_per_block - 1) / warps_per_block;
    edge_scatter_kernel<<<blocks, 256>>>(x, ei, W2, W3, out, n_edges);
}

// round 5
// speedup vs baseline: 1.0909x; 1.0909x over previous
#include <cuda_runtime.h>
#include <cstdint>

#define C 128

// Flag: 1 if edge_index is int64, 0 if int32 (deterministic per input).
__device__ int g_idx64;

__global__ void detect_idx_kernel(const void* __restrict__ ei, int n_nodes) {
    if (threadIdx.x == 0 && blockIdx.x == 0) {
        const long long* p = (const long long*)ei;
        int ok = 1;
        #pragma unroll
        for (int i = 0; i < 16; i++) {
            long long v = p[i];
            if (v < 0 || v >= (long long)n_nodes) { ok = 0; }
        }
        g_idx64 = ok;
    }
}

__device__ __forceinline__ float warp_sum(float v) {
    #pragma unroll
    for (int o = 16; o > 0; o >>= 1)
        v += __shfl_xor_sync(0xffffffffu, v, o);
    return v;
}

__device__ __forceinline__ void do_edge(
    const float* __restrict__ x, float* __restrict__ out,
    long long src, long long dst, int lane,
    float4 w2, float4 w3)
{
    float4 vs = __ldg((const float4*)(x + src * C) + lane);
    float4 vd = __ldg((const float4*)(x + dst * C) + lane);

    float part = vs.x * w3.x * vd.x
               + vs.y * w3.y * vd.y
               + vs.z * w3.z * vd.z
               + vs.w * w3.w * vd.w;
    float attn = warp_sum(part);

    float4 r;
    r.x = attn * vs.x * w2.x;
    r.y = attn * vs.y * w2.y;
    r.z = attn * vs.z * w2.z;
    r.w = attn * vs.w * w2.w;

    float* op = out + dst * C + lane * 4;
    asm volatile("red.global.add.v4.f32 [%0], {%1,%2,%3,%4};"
                 :: "l"(op), "f"(r.x), "f"(r.y), "f"(r.z), "f"(r.w)
                 : "memory");
}

// Grid-stride: each warp keeps W2/W3 in registers and processes many edges,
// 2 independent edges per iteration for MLP.
__global__ __launch_bounds__(256, 8) void edge_scatter_kernel(
    const float* __restrict__ x,
    const void* __restrict__ ei,
    const float* __restrict__ W2,
    const float* __restrict__ W3,
    float* __restrict__ out,
    int n_edges)
{
    const int lane = threadIdx.x & 31;
    const int warp_id = (int)((blockIdx.x * (unsigned)blockDim.x + threadIdx.x) >> 5);
    const int n_warps = (int)((gridDim.x * (unsigned)blockDim.x) >> 5);

    // Loaded ONCE per warp lifetime (was: per edge).
    const float4 w3 = __ldg((const float4*)W3 + lane);
    const float4 w2 = __ldg((const float4*)W2 + lane);

    const int idx64 = g_idx64;
    const long long* p64 = (const long long*)ei;
    const int*       p32 = (const int*)ei;

    for (int e = warp_id * 2; e < n_edges; e += n_warps * 2) {
        int e1 = e + 1;
        long long s0, d0, s1 = 0, d1 = 0;
        bool has1 = (e1 < n_edges);
        if (idx64) {
            s0 = __ldg(p64 + e);
            d0 = __ldg(p64 + n_edges + e);
            if (has1) { s1 = __ldg(p64 + e1); d1 = __ldg(p64 + n_edges + e1); }
        } else {
            s0 = (long long)__ldg(p32 + e);
            d0 = (long long)__ldg(p32 + n_edges + e);
            if (has1) { s1 = (long long)__ldg(p32 + e1);
                        d1 = (long long)__ldg(p32 + n_edges + e1); }
        }

        if (has1) {
            // Issue both edges' row loads back-to-back for MLP, then compute.
            float4 vs0 = __ldg((const float4*)(x + s0 * C) + lane);
            float4 vd0 = __ldg((const float4*)(x + d0 * C) + lane);
            float4 vs1 = __ldg((const float4*)(x + s1 * C) + lane);
            float4 vd1 = __ldg((const float4*)(x + d1 * C) + lane);

            float p0 = vs0.x * w3.x * vd0.x + vs0.y * w3.y * vd0.y
                     + vs0.z * w3.z * vd0.z + vs0.w * w3.w * vd0.w;
            float p1 = vs1.x * w3.x * vd1.x + vs1.y * w3.y * vd1.y
                     + vs1.z * w3.z * vd1.z + vs1.w * w3.w * vd1.w;

            // Two independent butterflies — interleave to hide SHFL latency.
            #pragma unroll
            for (int o = 16; o > 0; o >>= 1) {
                p0 += __shfl_xor_sync(0xffffffffu, p0, o);
                p1 += __shfl_xor_sync(0xffffffffu, p1, o);
            }
            float a0 = p0, a1 = p1;

            float4 r0, r1;
            r0.x = a0 * vs0.x * w2.x; r0.y = a0 * vs0.y * w2.y;
            r0.z = a0 * vs0.z * w2.z; r0.w = a0 * vs0.w * w2.w;
            r1.x = a1 * vs1.x * w2.x; r1.y = a1 * vs1.y * w2.y;
            r1.z = a1 * vs1.z * w2.z; r1.w = a1 * vs1.w * w2.w;

            float* op0 = out + d0 * C + lane * 4;
            float* op1 = out + d1 * C + lane * 4;
            asm volatile("red.global.add.v4.f32 [%0], {%1,%2,%3,%4};"
                         :: "l"(op0), "f"(r0.x), "f"(r0.y), "f"(r0.z), "f"(r0.w)
                         : "memory");
            asm volatile("red.global.add.v4.f32 [%0], {%1,%2,%3,%4};"
                         :: "l"(op1), "f"(r1.x), "f"(r1.y), "f"(r1.z), "f"(r1.w)
                         : "memory");
        } else {
            do_edge(x, out, s0, d0, lane, w2, w3);
        }
    }
}

extern "C" void kernel_launch(void* const* d_in, const int* in_sizes, int n_in,
                              void* d_out, int out_size) {
    const float* x  = (const float*)d_in[0];
    const void*  ei = d_in[1];
    const float* W2 = (const float*)d_in[2];
    const float* W3 = (const float*)d_in[3];
    float* out = (float*)d_out;

    int n_nodes = in_sizes[0] / C;
    int n_edges = in_sizes[1] / 2;

    cudaMemsetAsync(out, 0, (size_t)out_size * sizeof(float), 0);

    detect_idx_kernel<<<1, 32>>>(ei, n_nodes);

    // Fixed grid so each warp amortizes W-register loads over ~40 edges.
    int blocks = 2048;
    edge_scatter_kernel<<<blocks, 256>>>(x, ei, W2, W3, out, n_edges);
}

// round 6
// speedup vs baseline: 1.1412x; 1.0461x over previous
#include <cuda_runtime.h>
#include <cstdint>

#define C 128

// Flag: 1 if edge_index is int64, 0 if int32 (deterministic per input).
__device__ int g_idx64;

__global__ void detect_idx_kernel(const void* __restrict__ ei, int n_nodes) {
    if (threadIdx.x == 0 && blockIdx.x == 0) {
        const long long* p = (const long long*)ei;
        int ok = 1;
        #pragma unroll
        for (int i = 0; i < 16; i++) {
            long long v = p[i];
            if (v < 0 || v >= (long long)n_nodes) { ok = 0; }
        }
        g_idx64 = ok;
    }
}

// Warp = 4 groups of 8 lanes; each group processes one edge.
// Lane (group g, sub t) owns float4 indices {t, t+8, t+16, t+24} of the row.
__global__ __launch_bounds__(256, 4) void edge_scatter_kernel(
    const float* __restrict__ x,
    const void* __restrict__ ei,
    const float* __restrict__ W2,
    const float* __restrict__ W3,
    float* __restrict__ out,
    int n_edges)
{
    const int lane = threadIdx.x & 31;
    const int t = lane & 7;          // sub-lane within group
    const int grp = lane >> 3;       // group 0..3
    const int warp_id = (int)((blockIdx.x * (unsigned)blockDim.x + threadIdx.x) >> 5);
    const int n_warps = (int)((gridDim.x * (unsigned)blockDim.x) >> 5);

    // Per-lane weight slices, loaded once per warp lifetime.
    float4 w2v[4], w3v[4];
    #pragma unroll
    for (int k = 0; k < 4; k++) {
        w3v[k] = __ldg((const float4*)W3 + (t + 8 * k));
        w2v[k] = __ldg((const float4*)W2 + (t + 8 * k));
    }

    const int idx64 = g_idx64;
    const long long* p64 = (const long long*)ei;
    const int*       p32 = (const int*)ei;

    for (int base = warp_id * 4; base < n_edges; base += n_warps * 4) {
        int e = base + grp;
        bool valid = (e < n_edges);
        int ec = valid ? e : (n_edges - 1);

        long long src, dst;
        if (idx64) {
            src = __ldg(p64 + ec);
            dst = __ldg(p64 + n_edges + ec);
        } else {
            src = (long long)__ldg(p32 + ec);
            dst = (long long)__ldg(p32 + n_edges + ec);
        }

        const float4* srow = (const float4*)(x + src * C);
        const float4* drow = (const float4*)(x + dst * C);

        // 8 independent 16B loads in flight per lane pair of rows.
        float4 vs[4], vd[4];
        #pragma unroll
        for (int k = 0; k < 4; k++) vs[k] = __ldg(srow + (t + 8 * k));
        #pragma unroll
        for (int k = 0; k < 4; k++) vd[k] = __ldg(drow + (t + 8 * k));

        float part = 0.f;
        #pragma unroll
        for (int k = 0; k < 4; k++) {
            part += vs[k].x * w3v[k].x * vd[k].x
                  + vs[k].y * w3v[k].y * vd[k].y
                  + vs[k].z * w3v[k].z * vd[k].z
                  + vs[k].w * w3v[k].w * vd[k].w;
        }

        // Reduce across 8 lanes (xor offsets 4,2,1 stay within the group);
        // all 4 groups reduce concurrently in 3 shfl instructions.
        part += __shfl_xor_sync(0xffffffffu, part, 4);
        part += __shfl_xor_sync(0xffffffffu, part, 2);
        part += __shfl_xor_sync(0xffffffffu, part, 1);
        float attn = part;

        if (valid) {
            float* op = out + dst * C;
            #pragma unroll
            for (int k = 0; k < 4; k++) {
                float4 r;
                r.x = attn * vs[k].x * w2v[k].x;
                r.y = attn * vs[k].y * w2v[k].y;
                r.z = attn * vs[k].z * w2v[k].z;
                r.w = attn * vs[k].w * w2v[k].w;
                asm volatile("red.global.add.v4.f32 [%0], {%1,%2,%3,%4};"
                             :: "l"(op + (t + 8 * k) * 4),
                                "f"(r.x), "f"(r.y), "f"(r.z), "f"(r.w)
                             : "memory");
            }
        }
    }
}

extern "C" void kernel_launch(void* const* d_in, const int* in_sizes, int n_in,
                              void* d_out, int out_size) {
    const float* x  = (const float*)d_in[0];
    const void*  ei = d_in[1];
    const float* W2 = (const float*)d_in[2];
    const float* W3 = (const float*)d_in[3];
    float* out = (float*)d_out;

    int n_nodes = in_sizes[0] / C;
    int n_edges = in_sizes[1] / 2;

    cudaMemsetAsync(out, 0, (size_t)out_size * sizeof(float), 0);

    detect_idx_kernel<<<1, 32>>>(ei, n_nodes);

    int blocks = 2048;
    edge_scatter_kernel<<<blocks, 256>>>(x, ei, W2, W3, out, n_edges);
}

// round 7
// speedup vs baseline: 1.1707x; 1.0259x over previous
#include <cuda_runtime.h>
#include <cstdint>

#define C 128
#define N_MAX 16384
#define E_MAX 1100000

// Scratch (static __device__ — no allocs allowed)
__device__ int g_idx64;
__device__ int g_cnt[N_MAX + 1];
__device__ int g_off[N_MAX + 1];
__device__ int g_cur[N_MAX + 1];
__device__ int g_ssrc[E_MAX];

__global__ void detect_idx_kernel(const void* __restrict__ ei, int n_nodes) {
    if (threadIdx.x == 0 && blockIdx.x == 0) {
        const long long* p = (const long long*)ei;
        int ok = 1;
        #pragma unroll
        for (int i = 0; i < 16; i++) {
            long long v = p[i];
            if (v < 0 || v >= (long long)n_nodes) { ok = 0; }
        }
        g_idx64 = ok;
    }
}

__global__ void zero_counts_kernel(int n_nodes) {
    int i = blockIdx.x * blockDim.x + threadIdx.x;
    if (i <= n_nodes) g_cnt[i] = 0;
}

__global__ void histogram_kernel(const void* __restrict__ ei, int n_edges) {
    int i = blockIdx.x * blockDim.x + threadIdx.x;
    int stride = gridDim.x * blockDim.x;
    const int idx64 = g_idx64;
    const long long* p64 = (const long long*)ei + n_edges;  // dst half
    const int*       p32 = (const int*)ei + n_edges;
    for (int e = i; e < n_edges; e += stride) {
        int d = idx64 ? (int)__ldg(p64 + e) : __ldg(p32 + e);
        atomicAdd(&g_cnt[d], 1);
    }
}

// Single-block exclusive scan over g_cnt[0..n) -> g_off, g_cur; g_off[n]=total.
__global__ __launch_bounds__(1024) void scan_kernel(int n_nodes) {
    __shared__ int part[1024];
    int tid = threadIdx.x;
    int items = (n_nodes + 1023) >> 10;
    int b = tid * items;
    int local = 0;
    for (int k = 0; k < items; k++)
        if (b + k < n_nodes) local += g_cnt[b + k];
    part[tid] = local;
    __syncthreads();
    for (int o = 1; o < 1024; o <<= 1) {
        int v = (tid >= o) ? part[tid - o] : 0;
        __syncthreads();
        part[tid] += v;
        __syncthreads();
    }
    int run = (tid > 0) ? part[tid - 1] : 0;
    for (int k = 0; k < items; k++) {
        if (b + k < n_nodes) {
            g_off[b + k] = run;
            g_cur[b + k] = run;
            run += g_cnt[b + k];
        }
    }
    if (tid == 1023) g_off[n_nodes] = part[1023];
}

__global__ void scatter_kernel(const void* __restrict__ ei, int n_edges) {
    int i = blockIdx.x * blockDim.x + threadIdx.x;
    int stride = gridDim.x * blockDim.x;
    const int idx64 = g_idx64;
    const long long* p64 = (const long long*)ei;
    const int*       p32 = (const int*)ei;
    for (int e = i; e < n_edges; e += stride) {
        int s, d;
        if (idx64) {
            s = (int)__ldg(p64 + e);
            d = (int)__ldg(p64 + n_edges + e);
        } else {
            s = __ldg(p32 + e);
            d = __ldg(p32 + n_edges + e);
        }
        int pos = atomicAdd(&g_cur[d], 1);
        g_ssrc[pos] = s;
    }
}

// One warp per destination node. x[dst] row + accumulators live in registers;
// per edge: 1 idx load + 1 row load + 5 shfl. W2 applied once at the end.
__global__ __launch_bounds__(256) void gather_kernel(
    const float* __restrict__ x,
    const float* __restrict__ W2,
    const float* __restrict__ W3,
    float* __restrict__ out,
    int n_nodes)
{
    const int lane = threadIdx.x & 31;
    const int j = (int)((blockIdx.x * (unsigned)blockDim.x + threadIdx.x) >> 5);
    if (j >= n_nodes) return;

    float4 xj = __ldg((const float4*)(x + (long long)j * C) + lane);
    float4 w3 = __ldg((const float4*)W3 + lane);
    float4 w2 = __ldg((const float4*)W2 + lane);
    float4 w3xj;
    w3xj.x = w3.x * xj.x; w3xj.y = w3.y * xj.y;
    w3xj.z = w3.z * xj.z; w3xj.w = w3.w * xj.w;

    float4 acc = make_float4(0.f, 0.f, 0.f, 0.f);

    int beg = __ldg(&g_off[j]);
    int end = __ldg(&g_off[j + 1]);

    int i = beg;
    for (; i + 1 < end; i += 2) {
        int s0 = __ldg(&g_ssrc[i]);
        int s1 = __ldg(&g_ssrc[i + 1]);
        float4 v0 = __ldg((const float4*)(x + (long long)s0 * C) + lane);
        float4 v1 = __ldg((const float4*)(x + (long long)s1 * C) + lane);

        float p0 = v0.x * w3xj.x + v0.y * w3xj.y + v0.z * w3xj.z + v0.w * w3xj.w;
        float p1 = v1.x * w3xj.x + v1.y * w3xj.y + v1.z * w3xj.z + v1.w * w3xj.w;
        #pragma unroll
        for (int o = 16; o > 0; o >>= 1) {
            p0 += __shfl_xor_sync(0xffffffffu, p0, o);
            p1 += __shfl_xor_sync(0xffffffffu, p1, o);
        }
        acc.x += p0 * v0.x + p1 * v1.x;
        acc.y += p0 * v0.y + p1 * v1.y;
        acc.z += p0 * v0.z + p1 * v1.z;
        acc.w += p0 * v0.w + p1 * v1.w;
    }
    if (i < end) {
        int s0 = __ldg(&g_ssrc[i]);
        float4 v0 = __ldg((const float4*)(x + (long long)s0 * C) + lane);
        float p0 = v0.x * w3xj.x + v0.y * w3xj.y + v0.z * w3xj.z + v0.w * w3xj.w;
        #pragma unroll
        for (int o = 16; o > 0; o >>= 1)
            p0 += __shfl_xor_sync(0xffffffffu, p0, o);
        acc.x += p0 * v0.x;
        acc.y += p0 * v0.y;
        acc.z += p0 * v0.z;
        acc.w += p0 * v0.w;
    }

    float4 r;
    r.x = acc.x * w2.x; r.y = acc.y * w2.y;
    r.z = acc.z * w2.z; r.w = acc.w * w2.w;
    ((float4*)(out + (long long)j * C))[lane] = r;
}

// ---------------- Fallback (R5 kernel) for unexpected shapes ----------------
__global__ __launch_bounds__(256, 4) void edge_scatter_kernel(
    const float* __restrict__ x, const void* __restrict__ ei,
    const float* __restrict__ W2, const float* __restrict__ W3,
    float* __restrict__ out, int n_edges)
{
    const int lane = threadIdx.x & 31;
    const int t = lane & 7;
    const int grp = lane >> 3;
    const int warp_id = (int)((blockIdx.x * (unsigned)blockDim.x + threadIdx.x) >> 5);
    const int n_warps = (int)((gridDim.x * (unsigned)blockDim.x) >> 5);

    float4 w2v[4], w3v[4];
    #pragma unroll
    for (int k = 0; k < 4; k++) {
        w3v[k] = __ldg((const float4*)W3 + (t + 8 * k));
        w2v[k] = __ldg((const float4*)W2 + (t + 8 * k));
    }
    const int idx64 = g_idx64;
    const long long* p64 = (const long long*)ei;
    const int*       p32 = (const int*)ei;

    for (int base = warp_id * 4; base < n_edges; base += n_warps * 4) {
        int e = base + grp;
        bool valid = (e < n_edges);
        int ec = valid ? e : (n_edges - 1);
        long long src, dst;
        if (idx64) { src = __ldg(p64 + ec); dst = __ldg(p64 + n_edges + ec); }
        else { src = (long long)__ldg(p32 + ec); dst = (long long)__ldg(p32 + n_edges + ec); }

        const float4* srow = (const float4*)(x + src * C);
        const float4* drow = (const float4*)(x + dst * C);
        float4 vs[4], vd[4];
        #pragma unroll
        for (int k = 0; k < 4; k++) vs[k] = __ldg(srow + (t + 8 * k));
        #pragma unroll
        for (int k = 0; k < 4; k++) vd[k] = __ldg(drow + (t + 8 * k));

        float part = 0.f;
        #pragma unroll
        for (int k = 0; k < 4; k++)
            part += vs[k].x * w3v[k].x * vd[k].x + vs[k].y * w3v[k].y * vd[k].y
                  + vs[k].z * w3v[k].z * vd[k].z + vs[k].w * w3v[k].w * vd[k].w;
        part += __shfl_xor_sync(0xffffffffu, part, 4);
        part += __shfl_xor_sync(0xffffffffu, part, 2);
        part += __shfl_xor_sync(0xffffffffu, part, 1);

        if (valid) {
            float* op = out + dst * C;
            #pragma unroll
            for (int k = 0; k < 4; k++) {
                float4 r;
                r.x = part * vs[k].x * w2v[k].x; r.y = part * vs[k].y * w2v[k].y;
                r.z = part * vs[k].z * w2v[k].z; r.w = part * vs[k].w * w2v[k].w;
                asm volatile("red.global.add.v4.f32 [%0], {%1,%2,%3,%4};"
                             :: "l"(op + (t + 8 * k) * 4),
                                "f"(r.x), "f"(r.y), "f"(r.z), "f"(r.w) : "memory");
            }
        }
    }
}

extern "C" void kernel_launch(void* const* d_in, const int* in_sizes, int n_in,
                              void* d_out, int out_size) {
    const float* x  = (const float*)d_in[0];
    const void*  ei = d_in[1];
    const float* W2 = (const float*)d_in[2];
    const float* W3 = (const float*)d_in[3];
    float* out = (float*)d_out;

    int n_nodes = in_sizes[0] / C;
    int n_edges = in_sizes[1] / 2;

    detect_idx_kernel<<<1, 32>>>(ei, n_nodes);

    if (n_nodes <= N_MAX && n_edges <= E_MAX) {
        zero_counts_kernel<<<(n_nodes + 256) / 256, 256>>>(n_nodes);
        histogram_kernel<<<512, 256>>>(ei, n_edges);
        scan_kernel<<<1, 1024>>>(n_nodes);
        scatter_kernel<<<512, 256>>>(ei, n_edges);
        int warps_per_block = 256 / 32;
        int blocks = (n_nodes + warps_per_block - 1) / warps_per_block;
        gather_kernel<<<blocks, 256>>>(x, W2, W3, out, n_nodes);
    } else {
        cudaMemsetAsync(out, 0, (size_t)out_size * sizeof(float), 0);
        edge_scatter_kernel<<<2048, 256>>>(x, ei, W2, W3, out, n_edges);
    }
}

// round 8
// speedup vs baseline: 1.7114x; 1.4618x over previous
#include <cuda_runtime.h>
#include <cstdint>

#define C 128
#define N_MAX 16384
#define E_MAX 1100000
#define CAP 256

// Static scratch (no allocs allowed)
__device__ int g_idx64;
__device__ int g_cnt[N_MAX];
__device__ int g_ssrc[N_MAX * CAP];           // bucketed src ids (16 MB)
__device__ int g_ovf_cnt;
__device__ long long g_ovf[E_MAX];            // overflow edges, packed (src,dst)

__global__ void detect_idx_kernel(const void* __restrict__ ei, int n_nodes) {
    if (threadIdx.x == 0 && blockIdx.x == 0) {
        const long long* p = (const long long*)ei;
        int ok = 1;
        #pragma unroll
        for (int i = 0; i < 16; i++) {
            long long v = p[i];
            if (v < 0 || v >= (long long)n_nodes) { ok = 0; }
        }
        g_idx64 = ok;
    }
}

// Single pass: bucket edge sources by destination. No histogram, no scan.
__global__ void bucket_kernel(const void* __restrict__ ei, int n_edges) {
    int i = blockIdx.x * blockDim.x + threadIdx.x;
    int stride = gridDim.x * blockDim.x;
    const int idx64 = g_idx64;
    const long long* p64 = (const long long*)ei;
    const int*       p32 = (const int*)ei;
    for (int e = i; e < n_edges; e += stride) {
        int s, d;
        if (idx64) {
            s = (int)__ldg(p64 + e);
            d = (int)__ldg(p64 + n_edges + e);
        } else {
            s = __ldg(p32 + e);
            d = __ldg(p32 + n_edges + e);
        }
        int pos = atomicAdd(&g_cnt[d], 1);
        if (pos < CAP) {
            g_ssrc[d * CAP + pos] = s;
        } else {
            int o = atomicAdd(&g_ovf_cnt, 1);
            g_ovf[o] = ((long long)d << 32) | (unsigned)s;
        }
    }
}

// One warp per destination node; x[dst] + accumulators in registers,
// one plain float4 store per lane at the end. 4-edge unroll for MLP.
__global__ __launch_bounds__(256) void gather_kernel(
    const float* __restrict__ x,
    const float* __restrict__ W2,
    const float* __restrict__ W3,
    float* __restrict__ out,
    int n_nodes)
{
    const int lane = threadIdx.x & 31;
    const int j = (int)((blockIdx.x * (unsigned)blockDim.x + threadIdx.x) >> 5);
    if (j >= n_nodes) return;

    float4 xj = __ldg((const float4*)(x + (long long)j * C) + lane);
    float4 w3 = __ldg((const float4*)W3 + lane);
    float4 w2 = __ldg((const float4*)W2 + lane);
    float4 w3xj;
    w3xj.x = w3.x * xj.x; w3xj.y = w3.y * xj.y;
    w3xj.z = w3.z * xj.z; w3xj.w = w3.w * xj.w;

    float4 acc = make_float4(0.f, 0.f, 0.f, 0.f);

    int deg = __ldg(&g_cnt[j]);
    if (deg > CAP) deg = CAP;
    const int* bucket = &g_ssrc[j * CAP];

    int i = 0;
    for (; i + 3 < deg; i += 4) {
        int s0 = __ldg(bucket + i);
        int s1 = __ldg(bucket + i + 1);
        int s2 = __ldg(bucket + i + 2);
        int s3 = __ldg(bucket + i + 3);
        float4 v0 = __ldg((const float4*)(x + (long long)s0 * C) + lane);
        float4 v1 = __ldg((const float4*)(x + (long long)s1 * C) + lane);
        float4 v2 = __ldg((const float4*)(x + (long long)s2 * C) + lane);
        float4 v3 = __ldg((const float4*)(x + (long long)s3 * C) + lane);

        float p0 = v0.x * w3xj.x + v0.y * w3xj.y + v0.z * w3xj.z + v0.w * w3xj.w;
        float p1 = v1.x * w3xj.x + v1.y * w3xj.y + v1.z * w3xj.z + v1.w * w3xj.w;
        float p2 = v2.x * w3xj.x + v2.y * w3xj.y + v2.z * w3xj.z + v2.w * w3xj.w;
        float p3 = v3.x * w3xj.x + v3.y * w3xj.y + v3.z * w3xj.z + v3.w * w3xj.w;
        #pragma unroll
        for (int o = 16; o > 0; o >>= 1) {
            p0 += __shfl_xor_sync(0xffffffffu, p0, o);
            p1 += __shfl_xor_sync(0xffffffffu, p1, o);
            p2 += __shfl_xor_sync(0xffffffffu, p2, o);
            p3 += __shfl_xor_sync(0xffffffffu, p3, o);
        }
        acc.x += p0 * v0.x + p1 * v1.x + p2 * v2.x + p3 * v3.x;
        acc.y += p0 * v0.y + p1 * v1.y + p2 * v2.y + p3 * v3.y;
        acc.z += p0 * v0.z + p1 * v1.z + p2 * v2.z + p3 * v3.z;
        acc.w += p0 * v0.w + p1 * v1.w + p2 * v2.w + p3 * v3.w;
    }
    for (; i < deg; i++) {
        int s0 = __ldg(bucket + i);
        float4 v0 = __ldg((const float4*)(x + (long long)s0 * C) + lane);
        float p0 = v0.x * w3xj.x + v0.y * w3xj.y + v0.z * w3xj.z + v0.w * w3xj.w;
        #pragma unroll
        for (int o = 16; o > 0; o >>= 1)
            p0 += __shfl_xor_sync(0xffffffffu, p0, o);
        acc.x += p0 * v0.x;
        acc.y += p0 * v0.y;
        acc.z += p0 * v0.z;
        acc.w += p0 * v0.w;
    }

    float4 r;
    r.x = acc.x * w2.x; r.y = acc.y * w2.y;
    r.z = acc.z * w2.z; r.w = acc.w * w2.w;
    ((float4*)(out + (long long)j * C))[lane] = r;
}

// Process overflow edges (degree > CAP): one warp per edge, atomic add into out.
// For the expected input distribution this is an empty list (launch-only cost).
__global__ __launch_bounds__(256) void overflow_kernel(
    const float* __restrict__ x,
    const float* __restrict__ W2,
    const float* __restrict__ W3,
    float* __restrict__ out)
{
    const int lane = threadIdx.x & 31;
    const int n_warps = (int)((gridDim.x * (unsigned)blockDim.x) >> 5);
    const int warp_id = (int)((blockIdx.x * (unsigned)blockDim.x + threadIdx.x) >> 5);
    const int n = g_ovf_cnt;

    float4 w3 = __ldg((const float4*)W3 + lane);
    float4 w2 = __ldg((const float4*)W2 + lane);

    for (int e = warp_id; e < n; e += n_warps) {
        long long pk = g_ovf[e];
        long long src = (unsigned)(pk & 0xffffffffLL);
        long long dst = pk >> 32;

        float4 vs = __ldg((const float4*)(x + src * C) + lane);
        float4 vd = __ldg((const float4*)(x + dst * C) + lane);
        float part = vs.x * w3.x * vd.x + vs.y * w3.y * vd.y
                   + vs.z * w3.z * vd.z + vs.w * w3.w * vd.w;
        #pragma unroll
        for (int o = 16; o > 0; o >>= 1)
            part += __shfl_xor_sync(0xffffffffu, part, o);

        float4 r;
        r.x = part * vs.x * w2.x; r.y = part * vs.y * w2.y;
        r.z = part * vs.z * w2.z; r.w = part * vs.w * w2.w;
        float* op = out + dst * C + lane * 4;
        asm volatile("red.global.add.v4.f32 [%0], {%1,%2,%3,%4};"
                     :: "l"(op), "f"(r.x), "f"(r.y), "f"(r.z), "f"(r.w)
                     : "memory");
    }
}

// ---------------- Fallback (R5 kernel) for unexpected shapes ----------------
__global__ __launch_bounds__(256, 4) void edge_scatter_kernel(
    const float* __restrict__ x, const void* __restrict__ ei,
    const float* __restrict__ W2, const float* __restrict__ W3,
    float* __restrict__ out, int n_edges)
{
    const int lane = threadIdx.x & 31;
    const int t = lane & 7;
    const int grp = lane >> 3;
    const int warp_id = (int)((blockIdx.x * (unsigned)blockDim.x + threadIdx.x) >> 5);
    const int n_warps = (int)((gridDim.x * (unsigned)blockDim.x) >> 5);

    float4 w2v[4], w3v[4];
    #pragma unroll
    for (int k = 0; k < 4; k++) {
        w3v[k] = __ldg((const float4*)W3 + (t + 8 * k));
        w2v[k] = __ldg((const float4*)W2 + (t + 8 * k));
    }
    const int idx64 = g_idx64;
    const long long* p64 = (const long long*)ei;
    const int*       p32 = (const int*)ei;

    for (int base = warp_id * 4; base < n_edges; base += n_warps * 4) {
        int e = base + grp;
        bool valid = (e < n_edges);
        int ec = valid ? e : (n_edges - 1);
        long long src, dst;
        if (idx64) { src = __ldg(p64 + ec); dst = __ldg(p64 + n_edges + ec); }
        else { src = (long long)__ldg(p32 + ec); dst = (long long)__ldg(p32 + n_edges + ec); }

        const float4* srow = (const float4*)(x + src * C);
        const float4* drow = (const float4*)(x + dst * C);
        float4 vs[4], vd[4];
        #pragma unroll
        for (int k = 0; k < 4; k++) vs[k] = __ldg(srow + (t + 8 * k));
        #pragma unroll
        for (int k = 0; k < 4; k++) vd[k] = __ldg(drow + (t + 8 * k));

        float part = 0.f;
        #pragma unroll
        for (int k = 0; k < 4; k++)
            part += vs[k].x * w3v[k].x * vd[k].x + vs[k].y * w3v[k].y * vd[k].y
                  + vs[k].z * w3v[k].z * vd[k].z + vs[k].w * w3v[k].w * vd[k].w;
        part += __shfl_xor_sync(0xffffffffu, part, 4);
        part += __shfl_xor_sync(0xffffffffu, part, 2);
        part += __shfl_xor_sync(0xffffffffu, part, 1);

        if (valid) {
            float* op = out + dst * C;
            #pragma unroll
            for (int k = 0; k < 4; k++) {
                float4 r;
                r.x = part * vs[k].x * w2v[k].x; r.y = part * vs[k].y * w2v[k].y;
                r.z = part * vs[k].z * w2v[k].z; r.w = part * vs[k].w * w2v[k].w;
                asm volatile("red.global.add.v4.f32 [%0], {%1,%2,%3,%4};"
                             :: "l"(op + (t + 8 * k) * 4),
                                "f"(r.x), "f"(r.y), "f"(r.z), "f"(r.w) : "memory");
            }
        }
    }
}

extern "C" void kernel_launch(void* const* d_in, const int* in_sizes, int n_in,
                              void* d_out, int out_size) {
    const float* x  = (const float*)d_in[0];
    const void*  ei = d_in[1];
    const float* W2 = (const float*)d_in[2];
    const float* W3 = (const float*)d_in[3];
    float* out = (float*)d_out;

    int n_nodes = in_sizes[0] / C;
    int n_edges = in_sizes[1] / 2;

    detect_idx_kernel<<<1, 32>>>(ei, n_nodes);

    if (n_nodes <= N_MAX && n_edges <= E_MAX) {
        void* cnt_ptr = nullptr;
        void* ovf_ptr = nullptr;
        cudaGetSymbolAddress(&cnt_ptr, g_cnt);
        cudaGetSymbolAddress(&ovf_ptr, g_ovf_cnt);
        cudaMemsetAsync(cnt_ptr, 0, (size_t)n_nodes * sizeof(int), 0);
        cudaMemsetAsync(ovf_ptr, 0, sizeof(int), 0);

        bucket_kernel<<<512, 256>>>(ei, n_edges);

        int warps_per_block = 256 / 32;
        int blocks = (n_nodes + warps_per_block - 1) / warps_per_block;
        gather_kernel<<<blocks, 256>>>(x, W2, W3, out, n_nodes);

        overflow_kernel<<<32, 256>>>(x, W2, W3, out);
    } else {
        cudaMemsetAsync(out, 0, (size_t)out_size * sizeof(float), 0);
        edge_scatter_kernel<<<2048, 256>>>(x, ei, W2, W3, out, n_edges);
    }
}

// round 9
// speedup vs baseline: 1.7778x; 1.0388x over previous
#include <cuda_runtime.h>
#include <cuda_fp16.h>
#include <cstdint>

#define C 128
#define N_MAX 16384
#define E_MAX 1100000
#define CAP 256

// Static scratch (no allocs allowed)
__device__ int g_idx64;
__device__ int g_cnt[N_MAX];
__device__ int g_ssrc[N_MAX * CAP];           // bucketed src ids
__device__ int g_ovf_cnt;
__device__ long long g_ovf[E_MAX];            // overflow edges (src,dst)
__device__ __half g_xh[N_MAX * C];            // fp16 copy of x for gather stream

__global__ void detect_idx_kernel(const void* __restrict__ ei, int n_nodes) {
    if (threadIdx.x == 0 && blockIdx.x == 0) {
        const long long* p = (const long long*)ei;
        int ok = 1;
        #pragma unroll
        for (int i = 0; i < 16; i++) {
            long long v = p[i];
            if (v < 0 || v >= (long long)n_nodes) { ok = 0; }
        }
        g_idx64 = ok;
    }
}

// x (fp32) -> g_xh (fp16). One thread per float4.
__global__ void convert_kernel(const float* __restrict__ x, int n_f4) {
    int i = blockIdx.x * blockDim.x + threadIdx.x;
    if (i >= n_f4) return;
    float4 v = __ldg((const float4*)x + i);
    __half2 h0 = __floats2half2_rn(v.x, v.y);
    __half2 h1 = __floats2half2_rn(v.z, v.w);
    uint2 u;
    u.x = *reinterpret_cast<unsigned*>(&h0);
    u.y = *reinterpret_cast<unsigned*>(&h1);
    ((uint2*)g_xh)[i] = u;
}

// Bucket edge sources by destination; per-block inline idx-dtype detect.
__global__ void bucket_kernel(const void* __restrict__ ei, int n_edges, int n_nodes) {
    __shared__ int s_idx64;
    if (threadIdx.x == 0) {
        const long long* p = (const long long*)ei;
        int ok = 1;
        #pragma unroll
        for (int i = 0; i < 16; i++) {
            long long v = p[i];
            if (v < 0 || v >= (long long)n_nodes) { ok = 0; }
        }
        s_idx64 = ok;
    }
    __syncthreads();
    const int idx64 = s_idx64;

    int i = blockIdx.x * blockDim.x + threadIdx.x;
    int stride = gridDim.x * blockDim.x;
    const long long* p64 = (const long long*)ei;
    const int*       p32 = (const int*)ei;
    for (int e = i; e < n_edges; e += stride) {
        int s, d;
        if (idx64) {
            s = (int)__ldg(p64 + e);
            d = (int)__ldg(p64 + n_edges + e);
        } else {
            s = __ldg(p32 + e);
            d = __ldg(p32 + n_edges + e);
        }
        int pos = atomicAdd(&g_cnt[d], 1);
        if (pos < CAP) {
            g_ssrc[d * CAP + pos] = s;
        } else {
            int o = atomicAdd(&g_ovf_cnt, 1);
            g_ovf[o] = ((long long)d << 32) | (unsigned)s;
        }
    }
}

// One warp per destination node. Src rows streamed as fp16 (256B/row);
// dst row, weights, dot and accumulation all fp32.
__global__ __launch_bounds__(256) void gather_kernel(
    const float* __restrict__ x,
    const float* __restrict__ W2,
    const float* __restrict__ W3,
    float* __restrict__ out,
    int n_nodes)
{
    const int lane = threadIdx.x & 31;
    const int j = (int)((blockIdx.x * (unsigned)blockDim.x + threadIdx.x) >> 5);
    if (j >= n_nodes) return;

    float4 xj = __ldg((const float4*)(x + (long long)j * C) + lane);
    float4 w3 = __ldg((const float4*)W3 + lane);
    float4 w2 = __ldg((const float4*)W2 + lane);
    float4 w3xj;
    w3xj.x = w3.x * xj.x; w3xj.y = w3.y * xj.y;
    w3xj.z = w3.z * xj.z; w3xj.w = w3.w * xj.w;

    float4 acc = make_float4(0.f, 0.f, 0.f, 0.f);

    int deg = __ldg(&g_cnt[j]);
    if (deg > CAP) deg = CAP;
    const int* bucket = &g_ssrc[j * CAP];

    int i = 0;
    for (; i + 3 < deg; i += 4) {
        int4 sv = __ldg((const int4*)(bucket + i));   // 16B-aligned (i%4==0, base 1KB-aligned)

        uint2 u0 = __ldg((const uint2*)(g_xh + (long long)sv.x * C) + lane);
        uint2 u1 = __ldg((const uint2*)(g_xh + (long long)sv.y * C) + lane);
        uint2 u2 = __ldg((const uint2*)(g_xh + (long long)sv.z * C) + lane);
        uint2 u3 = __ldg((const uint2*)(g_xh + (long long)sv.w * C) + lane);

        float2 a0 = __half22float2(*(__half2*)&u0.x), b0 = __half22float2(*(__half2*)&u0.y);
        float2 a1 = __half22float2(*(__half2*)&u1.x), b1 = __half22float2(*(__half2*)&u1.y);
        float2 a2 = __half22float2(*(__half2*)&u2.x), b2 = __half22float2(*(__half2*)&u2.y);
        float2 a3 = __half22float2(*(__half2*)&u3.x), b3 = __half22float2(*(__half2*)&u3.y);

        float p0 = a0.x * w3xj.x + a0.y * w3xj.y + b0.x * w3xj.z + b0.y * w3xj.w;
        float p1 = a1.x * w3xj.x + a1.y * w3xj.y + b1.x * w3xj.z + b1.y * w3xj.w;
        float p2 = a2.x * w3xj.x + a2.y * w3xj.y + b2.x * w3xj.z + b2.y * w3xj.w;
        float p3 = a3.x * w3xj.x + a3.y * w3xj.y + b3.x * w3xj.z + b3.y * w3xj.w;
        #pragma unroll
        for (int o = 16; o > 0; o >>= 1) {
            p0 += __shfl_xor_sync(0xffffffffu, p0, o);
            p1 += __shfl_xor_sync(0xffffffffu, p1, o);
            p2 += __shfl_xor_sync(0xffffffffu, p2, o);
            p3 += __shfl_xor_sync(0xffffffffu, p3, o);
        }
        acc.x += p0 * a0.x + p1 * a1.x + p2 * a2.x + p3 * a3.x;
        acc.y += p0 * a0.y + p1 * a1.y + p2 * a2.y + p3 * a3.y;
        acc.z += p0 * b0.x + p1 * b1.x + p2 * b2.x + p3 * b3.x;
        acc.w += p0 * b0.y + p1 * b1.y + p2 * b2.y + p3 * b3.y;
    }
    for (; i < deg; i++) {
        int s0 = __ldg(bucket + i);
        uint2 u0 = __ldg((const uint2*)(g_xh + (long long)s0 * C) + lane);
        float2 a0 = __half22float2(*(__half2*)&u0.x), b0 = __half22float2(*(__half2*)&u0.y);
        float p0 = a0.x * w3xj.x + a0.y * w3xj.y + b0.x * w3xj.z + b0.y * w3xj.w;
        #pragma unroll
        for (int o = 16; o > 0; o >>= 1)
            p0 += __shfl_xor_sync(0xffffffffu, p0, o);
        acc.x += p0 * a0.x;
        acc.y += p0 * a0.y;
        acc.z += p0 * b0.x;
        acc.w += p0 * b0.y;
    }

    float4 r;
    r.x = acc.x * w2.x; r.y = acc.y * w2.y;
    r.z = acc.z * w2.z; r.w = acc.w * w2.w;
    ((float4*)(out + (long long)j * C))[lane] = r;
}

// Overflow edges (degree > CAP): fp32 path, atomic add. Early-exit when empty.
__global__ __launch_bounds__(256) void overflow_kernel(
    const float* __restrict__ x,
    const float* __restrict__ W2,
    const float* __restrict__ W3,
    float* __restrict__ out)
{
    const int n = g_ovf_cnt;
    if (n == 0) return;                 // expected path: exit before any W loads

    const int lane = threadIdx.x & 31;
    const int n_warps = (int)((gridDim.x * (unsigned)blockDim.x) >> 5);
    const int warp_id = (int)((blockIdx.x * (unsigned)blockDim.x + threadIdx.x) >> 5);

    float4 w3 = __ldg((const float4*)W3 + lane);
    float4 w2 = __ldg((const float4*)W2 + lane);

    for (int e = warp_id; e < n; e += n_warps) {
        long long pk = g_ovf[e];
        long long src = (unsigned)(pk & 0xffffffffLL);
        long long dst = pk >> 32;

        float4 vs = __ldg((const float4*)(x + src * C) + lane);
        float4 vd = __ldg((const float4*)(x + dst * C) + lane);
        float part = vs.x * w3.x * vd.x + vs.y * w3.y * vd.y
                   + vs.z * w3.z * vd.z + vs.w * w3.w * vd.w;
        #pragma unroll
        for (int o = 16; o > 0; o >>= 1)
            part += __shfl_xor_sync(0xffffffffu, part, o);

        float4 r;
        r.x = part * vs.x * w2.x; r.y = part * vs.y * w2.y;
        r.z = part * vs.z * w2.z; r.w = part * vs.w * w2.w;
        float* op = out + dst * C + lane * 4;
        asm volatile("red.global.add.v4.f32 [%0], {%1,%2,%3,%4};"
                     :: "l"(op), "f"(r.x), "f"(r.y), "f"(r.z), "f"(r.w)
                     : "memory");
    }
}

// ---------------- Fallback (R5 kernel) for unexpected shapes ----------------
__global__ __launch_bounds__(256, 4) void edge_scatter_kernel(
    const float* __restrict__ x, const void* __restrict__ ei,
    const float* __restrict__ W2, const float* __restrict__ W3,
    float* __restrict__ out, int n_edges)
{
    const int lane = threadIdx.x & 31;
    const int t = lane & 7;
    const int grp = lane >> 3;
    const int warp_id = (int)((blockIdx.x * (unsigned)blockDim.x + threadIdx.x) >> 5);
    const int n_warps = (int)((gridDim.x * (unsigned)blockDim.x) >> 5);

    float4 w2v[4], w3v[4];
    #pragma unroll
    for (int k = 0; k < 4; k++) {
        w3v[k] = __ldg((const float4*)W3 + (t + 8 * k));
        w2v[k] = __ldg((const float4*)W2 + (t + 8 * k));
    }
    const int idx64 = g_idx64;
    const long long* p64 = (const long long*)ei;
    const int*       p32 = (const int*)ei;

    for (int base = warp_id * 4; base < n_edges; base += n_warps * 4) {
        int e = base + grp;
        bool valid = (e < n_edges);
        int ec = valid ? e : (n_edges - 1);
        long long src, dst;
        if (idx64) { src = __ldg(p64 + ec); dst = __ldg(p64 + n_edges + ec); }
        else { src = (long long)__ldg(p32 + ec); dst = (long long)__ldg(p32 + n_edges + ec); }

        const float4* srow = (const float4*)(x + src * C);
        const float4* drow = (const float4*)(x + dst * C);
        float4 vs[4], vd[4];
        #pragma unroll
        for (int k = 0; k < 4; k++) vs[k] = __ldg(srow + (t + 8 * k));
        #pragma unroll
        for (int k = 0; k < 4; k++) vd[k] = __ldg(drow + (t + 8 * k));

        float part = 0.f;
        #pragma unroll
        for (int k = 0; k < 4; k++)
            part += vs[k].x * w3v[k].x * vd[k].x + vs[k].y * w3v[k].y * vd[k].y
                  + vs[k].z * w3v[k].z * vd[k].z + vs[k].w * w3v[k].w * vd[k].w;
        part += __shfl_xor_sync(0xffffffffu, part, 4);
        part += __shfl_xor_sync(0xffffffffu, part, 2);
        part += __shfl_xor_sync(0xffffffffu, part, 1);

        if (valid) {
            float* op = out + dst * C;
            #pragma unroll
            for (int k = 0; k < 4; k++) {
                float4 r;
                r.x = part * vs[k].x * w2v[k].x; r.y = part * vs[k].y * w2v[k].y;
                r.z = part * vs[k].z * w2v[k].z; r.w = part * vs[k].w * w2v[k].w;
                asm volatile("red.global.add.v4.f32 [%0], {%1,%2,%3,%4};"
                             :: "l"(op + (t + 8 * k) * 4),
                                "f"(r.x), "f"(r.y), "f"(r.z), "f"(r.w) : "memory");
            }
        }
    }
}

extern "C" void kernel_launch(void* const* d_in, const int* in_sizes, int n_in,
                              void* d_out, int out_size) {
    const float* x  = (const float*)d_in[0];
    const void*  ei = d_in[1];
    const float* W2 = (const float*)d_in[2];
    const float* W3 = (const float*)d_in[3];
    float* out = (float*)d_out;

    int n_nodes = in_sizes[0] / C;
    int n_edges = in_sizes[1] / 2;

    if (n_nodes <= N_MAX && n_edges <= E_MAX) {
        void* cnt_ptr = nullptr;
        void* ovf_ptr = nullptr;
        cudaGetSymbolAddress(&cnt_ptr, g_cnt);
        cudaGetSymbolAddress(&ovf_ptr, g_ovf_cnt);
        cudaMemsetAsync(cnt_ptr, 0, (size_t)n_nodes * sizeof(int), 0);
        cudaMemsetAsync(ovf_ptr, 0, sizeof(int), 0);

        int n_f4 = n_nodes * (C / 4);
        convert_kernel<<<(n_f4 + 255) / 256, 256>>>(x, n_f4);

        bucket_kernel<<<512, 256>>>(ei, n_edges, n_nodes);

        int warps_per_block = 256 / 32;
        int blocks = (n_nodes + warps_per_block - 1) / warps_per_block;
        gather_kernel<<<blocks, 256>>>(x, W2, W3, out, n_nodes);

        overflow_kernel<<<32, 256>>>(x, W2, W3, out);
    } else {
        detect_idx_kernel<<<1, 32>>>(ei, n_nodes);
        cudaMemsetAsync(out, 0, (size_t)out_size * sizeof(float), 0);
        edge_scatter_kernel<<<2048, 256>>>(x, ei, W2, W3, out, n_edges);
    }
}